// round 2
// baseline (speedup 1.0000x reference)
#include <cuda_runtime.h>
#include <cstdint>

#define G 512
#define NCELLS (G*G)          // 262144 cells
#define NBOX (NCELLS*2)       // 524288 boxes
#define NBINS 16384
#define WIN 2048
#define CAP 4096
#define MAXW 260
#define MAX_OUT 100

// ---------------- device scratch (static globals; no allocation) ----------------
__device__ float4 g_box[NBOX];                 // x1,y1,x2,y2
__device__ float  g_area[NBOX];
__device__ float  g_score[NBOX];
__device__ int    g_cls[NCELLS];               // class id per cell (shared by 2 anchors)
__device__ unsigned long long g_sorted[NBOX];  // binned (score,~idx) keys
__device__ int    g_hist[NBINS];
__device__ int    g_cnt[NBINS];
__device__ int    g_binStart[NBINS];
__device__ int    g_B[MAXW];                   // window boundary positions
__device__ int    g_total;

__device__ __forceinline__ unsigned binOf(float s){
    // monotone bin over (0.5, 1.0) -> [0..16383]; only called for s > 0.6
    return (__float_as_uint(s) - 0x3F000000u) >> 9;
}

// IOU > 0.5 test, float ops ordered exactly like the XLA reference:
// inter = max(ix2-ix1,0)*max(iy2-iy1,0); iou = inter / (area_a + area_b - inter + 1e-9)
__device__ __forceinline__ bool iou_gt(float4 a, float aa, float4 b, float ab){
    float ix1 = fmaxf(a.x, b.x);
    float iy1 = fmaxf(a.y, b.y);
    float ix2 = fminf(a.z, b.z);
    float iy2 = fminf(a.w, b.w);
    float iw  = fmaxf(__fsub_rn(ix2, ix1), 0.0f);
    float ih  = fmaxf(__fsub_rn(iy2, iy1), 0.0f);
    float inter = __fmul_rn(iw, ih);
    float den   = __fadd_rn(__fsub_rn(__fadd_rn(aa, ab), inter), 1e-9f);
    return __fdiv_rn(inter, den) > 0.5f;
}

// ---------------- K1: decode + score histogram ----------------
__global__ void k_decode(const float* __restrict__ in, const int* __restrict__ sq_p){
    int cell = blockIdx.x*blockDim.x + threadIdx.x;
    if (cell >= NCELLS) return;
    int i = cell >> 9;         // row
    int j = cell & (G-1);      // col
    const float4* p = reinterpret_cast<const float4*>(in + (size_t)cell*100);
    float4 v0 = p[0];   // obj0 obj1 cx0 cy0
    float4 v1 = p[1];   // w0 h0 cx1 cy1
    float4 v2 = p[2];   // w1 h1 cls0 cls1
    // class max / first-occurrence argmax over 90 classes (channels 10..99)
    float m = v2.z; int am = 0;
    if (v2.w > m){ m = v2.w; am = 1; }
    #pragma unroll
    for (int k = 3; k < 25; k++){
        float4 v = p[k];
        int base = (k-3)*4 + 2;
        if (v.x > m){ m = v.x; am = base;   }
        if (v.y > m){ m = v.y; am = base+1; }
        if (v.z > m){ m = v.z; am = base+2; }
        if (v.w > m){ m = v.w; am = base+3; }
    }
    g_cls[cell] = am;
    int sq = *sq_p;
    float jf = (float)j, iff = (float)i;
    float obj[2]; obj[0] = v0.x; obj[1] = v0.y;
    float rcx[2]; rcx[0] = v0.z; rcx[1] = v1.z;
    float rcy[2]; rcy[0] = v0.w; rcy[1] = v1.w;
    float rw[2];  rw[0]  = v1.x; rw[1]  = v2.x;
    float rh[2];  rh[0]  = v1.y; rh[1]  = v2.y;
    #pragma unroll
    for (int a = 0; a < 2; a++){
        float cx = __fmul_rn(__fadd_rn(rcx[a], jf), 16.0f);
        float cy = __fmul_rn(__fadd_rn(rcy[a], iff), 16.0f);
        float w = rw[a], h = rh[a];
        if (sq){ w = __fmul_rn(w, w); h = __fmul_rn(h, h); }
        w = __fmul_rn(w, 8192.0f);
        h = __fmul_rn(h, 8192.0f);
        float hw = __fmul_rn(w, 0.5f), hh = __fmul_rn(h, 0.5f);   // exact
        float x1 = __fsub_rn(cx, hw);
        float y1 = __fsub_rn(cy, hh);
        float x2 = __fsub_rn(__fadd_rn(cx, hw), 1.0f);
        float y2 = __fsub_rn(__fadd_rn(cy, hh), 1.0f);
        float area = __fmul_rn(fmaxf(__fsub_rn(x2, x1), 0.0f),
                               fmaxf(__fsub_rn(y2, y1), 0.0f));
        float sc = __fmul_rn(m, obj[a]);
        int idx = cell*2 + a;
        g_box[idx]   = make_float4(x1, y1, x2, y2);
        g_area[idx]  = area;
        g_score[idx] = sc;
        if (sc > 0.6f) atomicAdd(&g_hist[binOf(sc)], 1);
    }
}

// ---------------- K2: suffix-sum over bins (descending score) + window boundaries --
__global__ void k_scan(){
    extern __shared__ int sm[];   // NBINS ints: start of each descending-order bin
    __shared__ int part[1024];
    int tid = threadIdx.x;
    const int PER = NBINS/1024;   // 16
    int base = tid*PER;
    int vals[PER];
    int run = 0;
    #pragma unroll
    for (int t = 0; t < PER; t++){
        int v = g_hist[(NBINS-1) - (base + t)];
        vals[t] = run;
        run += v;
    }
    part[tid] = run;
    __syncthreads();
    for (int d = 1; d < 1024; d <<= 1){
        int v = (tid >= d) ? part[tid - d] : 0;
        __syncthreads();
        part[tid] += v;
        __syncthreads();
    }
    int off = part[tid] - run;   // exclusive block offset
    int T   = part[1023];
    #pragma unroll
    for (int t = 0; t < PER; t++){
        int j = base + t;
        int s = off + vals[t];
        sm[j] = s;
        g_binStart[(NBINS-1) - j] = s;
    }
    if (tid == 0){ g_total = T; g_B[0] = 0; }
    for (int k = tid; k < MAXW; k += 1024) if (k > 0) g_B[k] = T;
    __syncthreads();
    // B[k] = smallest bin start >= k*WIN (bin-aligned window boundaries)
    #pragma unroll
    for (int t = 0; t < PER; t++){
        int j = base + t;
        if (j == 0) continue;
        int s  = sm[j];
        int sp = sm[j-1];
        for (int k = sp/WIN + 1; k*WIN <= s && k < MAXW; k++) g_B[k] = s;
    }
}

// ---------------- K3: compact candidates into binned key array ----------------
__global__ void k_scatter(){
    int idx = blockIdx.x*blockDim.x + threadIdx.x;
    if (idx >= NBOX) return;
    float s = g_score[idx];
    if (s > 0.6f){
        unsigned b = binOf(s);
        int pos = g_binStart[b] + atomicAdd(&g_cnt[b], 1);
        unsigned long long key = ((unsigned long long)__float_as_uint(s) << 32)
                               | (unsigned long long)(0xFFFFFFFFu - (unsigned)idx);
        g_sorted[pos] = key;
    }
}

// ---------------- K4: single-CTA exact greedy NMS + output write ----------------
#define SM_CBOX   0
#define SM_KEYS   (CAP*16)
#define SM_CAREA  (CAP*24)
#define SM_KBOX   (CAP*28)
#define SM_KAREA  (SM_KBOX + MAX_OUT*16)
#define SM_KIDX   (SM_KAREA + MAX_OUT*4)
#define SM_ALIVE  (SM_KIDX + MAX_OUT*4)
#define SMEM_NMS  (SM_ALIVE + (CAP/32)*4 + 64)

__global__ void k_nms(float* __restrict__ out, int out_size){
    extern __shared__ char smraw[];
    float4* cbox  = (float4*)(smraw + SM_CBOX);
    unsigned long long* keys = (unsigned long long*)(smraw + SM_KEYS);
    float*  carea = (float*)(smraw + SM_CAREA);
    float4* kbox  = (float4*)(smraw + SM_KBOX);
    float*  karea = (float*)(smraw + SM_KAREA);
    int*    kidx  = (int*)(smraw + SM_KIDX);
    unsigned* alive = (unsigned*)(smraw + SM_ALIVE);
    __shared__ int s_nk, s_sel, s_done, s_frozen;
    int tid = threadIdx.x;
    if (tid == 0){ s_nk = 0; s_done = 0; s_frozen = 0; }
    __syncthreads();
    int T = g_total;

    for (int w = 0; w < MAXW-1; w++){
        int lo = g_B[w], hi = g_B[w+1];
        if (lo >= T) break;
        if (hi <= lo) continue;
        int size = hi - lo; if (size > CAP) size = CAP;  // safety clamp
        int n2 = 1; while (n2 < size) n2 <<= 1;
        for (int c = tid; c < n2; c += 1024)
            keys[c] = (c < size) ? g_sorted[lo + c] : 0ULL;
        __syncthreads();
        // bitonic sort descending by (score, ~idx) => score desc, idx asc on ties
        for (int kk = 2; kk <= n2; kk <<= 1){
            for (int jj = kk >> 1; jj > 0; jj >>= 1){
                for (int c = tid; c < n2; c += 1024){
                    int cx = c ^ jj;
                    if (cx > c){
                        unsigned long long a = keys[c], b = keys[cx];
                        bool sw = ((c & kk) == 0) ? (a < b) : (a > b);
                        if (sw){ keys[c] = b; keys[cx] = a; }
                    }
                }
                __syncthreads();
            }
        }
        int nwords = (size + 31) >> 5;
        for (int wd = tid; wd < nwords; wd += 1024){
            int rem = size - wd*32;
            alive[wd] = (rem >= 32) ? 0xFFFFFFFFu : ((1u << rem) - 1u);
        }
        for (int c = tid; c < size; c += 1024){
            unsigned idx = 0xFFFFFFFFu - (unsigned)(keys[c] & 0xFFFFFFFFull);
            cbox[c]  = g_box[idx];
            carea[c] = g_area[idx];
        }
        __syncthreads();
        // prefilter this window against boxes kept in prior windows
        int nk0 = s_nk;
        if (nk0 > 0){
            for (int c = tid; c < size; c += 1024){
                float ab = carea[c];
                bool sup = false;
                for (int k = 0; k < nk0; k++)
                    if (iou_gt(cbox[c], ab, kbox[k], karea[k])) { sup = true; break; }
                if (sup) atomicAnd(&alive[c >> 5], ~(1u << (c & 31)));
            }
        }
        __syncthreads();
        // iterative: first-alive (== argmax since sorted) then suppress
        int p0 = 0;  // thread0's monotone word scan pointer
        while (true){
            if (tid == 0){
                int sel = -1;
                while (p0 < nwords){
                    unsigned v = alive[p0];
                    if (v){ sel = p0*32 + (__ffs(v) - 1); break; }
                    p0++;
                }
                s_sel = sel;
                if (sel >= 0){
                    int nk = s_nk;
                    float a = carea[sel];
                    kbox[nk]  = cbox[sel];
                    karea[nk] = a;
                    kidx[nk]  = (int)(0xFFFFFFFFu - (unsigned)(keys[sel] & 0xFFFFFFFFull));
                    s_nk = nk + 1;
                    alive[sel >> 5] &= ~(1u << (sel & 31));
                    // Reference semantics: selected box removes itself only via
                    // self-IOU = a / ((a+a-a) + 1e-9) > 0.5. If NOT, it stays
                    // active forever and argmax re-selects it for every
                    // remaining slot -> freeze on this box.
                    float sden = __fadd_rn(__fsub_rn(__fadd_rn(a, a), a), 1e-9f);
                    if (!(__fdiv_rn(a, sden) > 0.5f)){
                        s_frozen = 1; s_done = 1;
                    } else if (nk + 1 == MAX_OUT){
                        s_done = 1;
                    }
                }
            }
            __syncthreads();
            int sel = s_sel;
            if (sel < 0) break;
            if (s_done) break;
            float4 sb = cbox[sel]; float sa = carea[sel];
            for (int c = tid; c < size; c += 1024){
                if (alive[c >> 5] & (1u << (c & 31))){
                    if (iou_gt(cbox[c], carea[c], sb, sa))
                        atomicAnd(&alive[c >> 5], ~(1u << (c & 31)));
                }
            }
            __syncthreads();
        }
        __syncthreads();
        if (s_done) break;
    }

    // write output: [boxes(100,4) | cls_ids(100) | scores(100) | valid(100)] as f32
    __syncthreads();
    if (tid < MAX_OUT){
        int k = tid;
        int nk = s_nk;
        // frozen: reference repeats the last kept (immortal) box for all
        // remaining iterations, all marked valid.
        int src = (k < nk) ? k : (s_frozen ? nk - 1 : -1);
        if (src >= 0){
            int idx = kidx[src];
            float4 b = g_box[idx];
            if (k*4+3 < out_size){
                out[k*4+0] = b.x; out[k*4+1] = b.y; out[k*4+2] = b.z; out[k*4+3] = b.w;
            }
            if (400+k < out_size) out[400+k] = (float)g_cls[idx >> 1];
            if (500+k < out_size) out[500+k] = g_score[idx];
            if (600+k < out_size) out[600+k] = 1.0f;
        } else {
            if (k*4+3 < out_size){
                out[k*4+0] = 0.0f; out[k*4+1] = 0.0f; out[k*4+2] = 0.0f; out[k*4+3] = 0.0f;
            }
            if (400+k < out_size) out[400+k] = -1.0f;
            if (500+k < out_size) out[500+k] = 0.0f;
            if (600+k < out_size) out[600+k] = 0.0f;
        }
    }
}

// ---------------- fallback: extract_boxes == 0 -> raw den_boxes ----------------
__global__ void k_rawboxes(const float* __restrict__ in, const int* __restrict__ sq_p,
                           float* __restrict__ out){
    int cell = blockIdx.x*blockDim.x + threadIdx.x;
    if (cell >= NCELLS) return;
    int i = cell >> 9, j = cell & (G-1);
    const float4* p = reinterpret_cast<const float4*>(in + (size_t)cell*100);
    float4 v0 = p[0]; float4 v1 = p[1]; float4 v2 = p[2];
    int sq = *sq_p;
    float jf = (float)j, iff = (float)i;
    float rcx[2] = {v0.z, v1.z}, rcy[2] = {v0.w, v1.w};
    float rw[2]  = {v1.x, v2.x}, rh[2]  = {v1.y, v2.y};
    #pragma unroll
    for (int a = 0; a < 2; a++){
        float cx = __fmul_rn(__fadd_rn(rcx[a], jf), 16.0f);
        float cy = __fmul_rn(__fadd_rn(rcy[a], iff), 16.0f);
        float w = rw[a], h = rh[a];
        if (sq){ w = __fmul_rn(w, w); h = __fmul_rn(h, h); }
        w = __fmul_rn(w, 8192.0f);
        h = __fmul_rn(h, 8192.0f);
        int idx = cell*2 + a;
        ((float4*)out)[idx] = make_float4(cx, cy, w, h);
    }
}

// ---------------- launch ----------------
extern "C" void kernel_launch(void* const* d_in, const int* in_sizes, int n_in,
                              void* d_out, int out_size){
    const float* in = (const float*)d_in[0];
    const int*   sq = (const int*)d_in[1];

    if (out_size >= NBOX*4){   // extract_boxes == 0 path
        k_rawboxes<<<NCELLS/256, 256>>>(in, sq, (float*)d_out);
        return;
    }

    void* histAddr = nullptr; cudaGetSymbolAddress(&histAddr, g_hist);
    void* cntAddr  = nullptr; cudaGetSymbolAddress(&cntAddr,  g_cnt);
    cudaMemsetAsync(histAddr, 0, NBINS*sizeof(int));
    cudaMemsetAsync(cntAddr,  0, NBINS*sizeof(int));

    cudaFuncSetAttribute(k_scan, cudaFuncAttributeMaxDynamicSharedMemorySize, NBINS*4);
    cudaFuncSetAttribute(k_nms,  cudaFuncAttributeMaxDynamicSharedMemorySize, SMEM_NMS);

    k_decode<<<NCELLS/256, 256>>>(in, sq);
    k_scan<<<1, 1024, NBINS*4>>>();
    k_scatter<<<NBOX/256, 256>>>();
    k_nms<<<1, 1024, SMEM_NMS>>>((float*)d_out, out_size);
}

// round 3
// speedup vs baseline: 1.0968x; 1.0968x over previous
#include <cuda_runtime.h>
#include <cstdint>

#define G 512
#define NCELLS (G*G)          // 262144 cells
#define NBOX (NCELLS*2)       // 524288 boxes
#define NBINS 16384
#define WIN 384
#define CAP 512
#define SLOTS (CAP/32)        // 16 keys per lane
#define MAXW 1400
#define MAX_OUT 100

// ---------------- device scratch (static globals; no allocation) ----------------
__device__ float4 g_box[NBOX];                 // x1,y1,x2,y2
__device__ float  g_area[NBOX];
__device__ float  g_score[NBOX];
__device__ int    g_cls[NCELLS];               // class id per cell (shared by 2 anchors)
__device__ unsigned long long g_sorted[NBOX];  // binned (score,~idx) keys
__device__ int    g_hist[NBINS];
__device__ int    g_cnt[NBINS];
__device__ int    g_binStart[NBINS];
__device__ int    g_B[MAXW];                   // window boundary positions
__device__ int    g_total;

__device__ __forceinline__ unsigned binOf(float s){
    return (__float_as_uint(s) - 0x3F000000u) >> 9;
}

// IOU > 0.5, float ops ordered exactly like the XLA reference.
__device__ __forceinline__ bool iou_gt(float4 a, float aa, float4 b, float ab){
    float ix1 = fmaxf(a.x, b.x);
    float iy1 = fmaxf(a.y, b.y);
    float ix2 = fminf(a.z, b.z);
    float iy2 = fminf(a.w, b.w);
    float iw  = fmaxf(__fsub_rn(ix2, ix1), 0.0f);
    float ih  = fmaxf(__fsub_rn(iy2, iy1), 0.0f);
    float inter = __fmul_rn(iw, ih);
    float den   = __fadd_rn(__fsub_rn(__fadd_rn(aa, ab), inter), 1e-9f);
    return __fdiv_rn(inter, den) > 0.5f;
}

__device__ __forceinline__ unsigned long long shflx_u64(unsigned long long v, int m){
    return __shfl_xor_sync(0xFFFFFFFFu, v, m);
}

// ---------------- K1: decode + score histogram (smem-staged coalesced loads) ------
#define TILE 128
#define CSTRIDE 27   // float4 stride per cell in smem (27t mod 32 bijective -> no conflicts)
__global__ void k_decode(const float* __restrict__ in, const int* __restrict__ sq_p){
    extern __shared__ float4 sm[];   // TILE*CSTRIDE float4 = 55296 B
    int tid = threadIdx.x;
    int cell0 = blockIdx.x * TILE;
    const float4* gp = reinterpret_cast<const float4*>(in) + (size_t)cell0 * 25;
    #pragma unroll
    for (int k = tid; k < TILE*25; k += TILE){
        int c = k / 25, r = k % 25;
        sm[c*CSTRIDE + r] = gp[k];
    }
    __syncthreads();
    int cell = cell0 + tid;
    int i = cell >> 9;         // row
    int j = cell & (G-1);      // col
    const float4* p = &sm[tid*CSTRIDE];
    float4 v0 = p[0];   // obj0 obj1 cx0 cy0
    float4 v1 = p[1];   // w0 h0 cx1 cy1
    float4 v2 = p[2];   // w1 h1 cls0 cls1
    // class max / first-occurrence argmax over 90 classes (channels 10..99)
    float m = v2.z; int am = 0;
    if (v2.w > m){ m = v2.w; am = 1; }
    #pragma unroll
    for (int k = 3; k < 25; k++){
        float4 v = p[k];
        int base = (k-3)*4 + 2;
        if (v.x > m){ m = v.x; am = base;   }
        if (v.y > m){ m = v.y; am = base+1; }
        if (v.z > m){ m = v.z; am = base+2; }
        if (v.w > m){ m = v.w; am = base+3; }
    }
    g_cls[cell] = am;
    int sq = *sq_p;
    float jf = (float)j, iff = (float)i;
    float obj[2]; obj[0] = v0.x; obj[1] = v0.y;
    float rcx[2]; rcx[0] = v0.z; rcx[1] = v1.z;
    float rcy[2]; rcy[0] = v0.w; rcy[1] = v1.w;
    float rw[2];  rw[0]  = v1.x; rw[1]  = v2.x;
    float rh[2];  rh[0]  = v1.y; rh[1]  = v2.y;
    #pragma unroll
    for (int a = 0; a < 2; a++){
        float cx = __fmul_rn(__fadd_rn(rcx[a], jf), 16.0f);
        float cy = __fmul_rn(__fadd_rn(rcy[a], iff), 16.0f);
        float w = rw[a], h = rh[a];
        if (sq){ w = __fmul_rn(w, w); h = __fmul_rn(h, h); }
        w = __fmul_rn(w, 8192.0f);
        h = __fmul_rn(h, 8192.0f);
        float hw = __fmul_rn(w, 0.5f), hh = __fmul_rn(h, 0.5f);   // exact
        float x1 = __fsub_rn(cx, hw);
        float y1 = __fsub_rn(cy, hh);
        float x2 = __fsub_rn(__fadd_rn(cx, hw), 1.0f);
        float y2 = __fsub_rn(__fadd_rn(cy, hh), 1.0f);
        float area = __fmul_rn(fmaxf(__fsub_rn(x2, x1), 0.0f),
                               fmaxf(__fsub_rn(y2, y1), 0.0f));
        float sc = __fmul_rn(m, obj[a]);
        int idx = cell*2 + a;
        g_box[idx]   = make_float4(x1, y1, x2, y2);
        g_area[idx]  = area;
        g_score[idx] = sc;
        if (sc > 0.6f) atomicAdd(&g_hist[binOf(sc)], 1);
    }
}

// ---------------- K2: suffix-sum over bins (descending score) + window boundaries --
__global__ void k_scan(){
    extern __shared__ int smi[];   // NBINS ints: descending-order bin starts
    __shared__ int part[1024];
    int tid = threadIdx.x;
    const int PER = NBINS/1024;   // 16
    int base = tid*PER;
    int vals[PER];
    int run = 0;
    #pragma unroll
    for (int t = 0; t < PER; t++){
        int v = g_hist[(NBINS-1) - (base + t)];
        vals[t] = run;
        run += v;
    }
    part[tid] = run;
    __syncthreads();
    for (int d = 1; d < 1024; d <<= 1){
        int v = (tid >= d) ? part[tid - d] : 0;
        __syncthreads();
        part[tid] += v;
        __syncthreads();
    }
    int off = part[tid] - run;   // exclusive block offset
    int T   = part[1023];
    #pragma unroll
    for (int t = 0; t < PER; t++){
        int j = base + t;
        int s = off + vals[t];
        smi[j] = s;
        g_binStart[(NBINS-1) - j] = s;
    }
    if (tid == 0){ g_total = T; g_B[0] = 0; }
    for (int k = tid; k < MAXW; k += 1024) if (k > 0) g_B[k] = T;
    __syncthreads();
    // B[k] = smallest bin start >= k*WIN (bin-aligned window boundaries)
    #pragma unroll
    for (int t = 0; t < PER; t++){
        int j = base + t;
        if (j == 0) continue;
        int s  = smi[j];
        int sp = smi[j-1];
        for (int k = sp/WIN + 1; k*WIN <= s && k < MAXW; k++) g_B[k] = s;
    }
}

// ---------------- K3: compact candidates into binned key array ----------------
__global__ void k_scatter(){
    int idx = blockIdx.x*blockDim.x + threadIdx.x;
    if (idx >= NBOX) return;
    float s = g_score[idx];
    if (s > 0.6f){
        unsigned b = binOf(s);
        int pos = g_binStart[b] + atomicAdd(&g_cnt[b], 1);
        unsigned long long key = ((unsigned long long)__float_as_uint(s) << 32)
                               | (unsigned long long)(0xFFFFFFFFu - (unsigned)idx);
        g_sorted[pos] = key;
    }
}

// ---------------- K4: single-WARP sort-free exact greedy NMS ----------------
__global__ void k_nms(float* __restrict__ out, int out_size){
    __shared__ float4 cbox[CAP];
    __shared__ float  carea[CAP];
    __shared__ float4 kbox[MAX_OUT];
    __shared__ float  karea[MAX_OUT];
    __shared__ int    kidx[MAX_OUT];
    int lane = threadIdx.x;
    int nk = 0, frozen = 0;
    int T = g_total;

    for (int w = 0; w < MAXW-1 && !frozen && nk < MAX_OUT; w++){
        int lo = g_B[w], hi = g_B[w+1];
        if (lo >= T) break;
        if (hi <= lo) continue;
        int size = hi - lo; if (size > CAP) size = CAP;

        unsigned long long key[SLOTS];
        unsigned am = 0;   // alive mask, bit t = slot t
        #pragma unroll
        for (int t = 0; t < SLOTS; t++){
            int c = t*32 + lane;
            unsigned long long k = (c < size) ? g_sorted[lo + c] : 0ULL;
            key[t] = k;
            if (k){
                unsigned idx = 0xFFFFFFFFu - (unsigned)(k & 0xFFFFFFFFull);
                cbox[c]  = g_box[idx];
                carea[c] = g_area[idx];
                am |= (1u << t);
            }
        }
        __syncwarp();
        // prefilter this window against boxes kept in prior windows
        #pragma unroll
        for (int t = 0; t < SLOTS; t++){
            if (am & (1u << t)){
                int c = t*32 + lane;
                float4 b = cbox[c]; float ab = carea[c];
                for (int k2 = 0; k2 < nk; k2++)
                    if (iou_gt(b, ab, kbox[k2], karea[k2])){ am &= ~(1u << t); break; }
            }
        }
        // selection loop: register+shfl argmax (exact: key = (score, ~idx))
        while (true){
            unsigned long long best = 0;
            #pragma unroll
            for (int t = 0; t < SLOTS; t++)
                if (((am >> t) & 1) && key[t] > best) best = key[t];
            #pragma unroll
            for (int off = 16; off; off >>= 1){
                unsigned long long o = shflx_u64(best, off);
                if (o > best) best = o;
            }
            if (best == 0) break;   // window exhausted
            int myc = -1;
            #pragma unroll
            for (int t = 0; t < SLOTS; t++)
                if (((am >> t) & 1) && key[t] == best) myc = t*32 + lane;
            unsigned bal = __ballot_sync(0xFFFFFFFFu, myc >= 0);
            int src  = __ffs(bal) - 1;
            int selc = __shfl_sync(0xFFFFFFFFu, myc, src);
            if (lane == src) am &= ~(1u << (selc >> 5));
            float4 sb = cbox[selc]; float sa = carea[selc];  // smem broadcast
            if (lane == 0){
                kbox[nk]  = sb;
                karea[nk] = sa;
                kidx[nk]  = (int)(0xFFFFFFFFu - (unsigned)(best & 0xFFFFFFFFull));
            }
            nk++;
            // Reference: selected box removes itself only if self-IOU
            // a / ((a+a-a)+1e-9) > 0.5; otherwise it is re-selected forever.
            float sden = __fadd_rn(__fsub_rn(__fadd_rn(sa, sa), sa), 1e-9f);
            if (!(__fdiv_rn(sa, sden) > 0.5f)){ frozen = 1; break; }
            if (nk == MAX_OUT) break;
            #pragma unroll
            for (int t = 0; t < SLOTS; t++){
                if ((am >> t) & 1){
                    int c = t*32 + lane;
                    if (iou_gt(cbox[c], carea[c], sb, sa)) am &= ~(1u << t);
                }
            }
        }
        __syncwarp();
    }

    __syncwarp();
    // output: [boxes(100,4) | cls_ids(100) | scores(100) | valid(100)] as f32
    for (int k = lane; k < MAX_OUT; k += 32){
        int src = (k < nk) ? k : (frozen ? nk - 1 : -1);
        if (src >= 0){
            int idx = kidx[src];
            float4 b = g_box[idx];
            if (k*4+3 < out_size){
                out[k*4+0] = b.x; out[k*4+1] = b.y; out[k*4+2] = b.z; out[k*4+3] = b.w;
            }
            if (400+k < out_size) out[400+k] = (float)g_cls[idx >> 1];
            if (500+k < out_size) out[500+k] = g_score[idx];
            if (600+k < out_size) out[600+k] = 1.0f;
        } else {
            if (k*4+3 < out_size){
                out[k*4+0] = 0.0f; out[k*4+1] = 0.0f; out[k*4+2] = 0.0f; out[k*4+3] = 0.0f;
            }
            if (400+k < out_size) out[400+k] = -1.0f;
            if (500+k < out_size) out[500+k] = 0.0f;
            if (600+k < out_size) out[600+k] = 0.0f;
        }
    }
}

// ---------------- fallback: extract_boxes == 0 -> raw den_boxes ----------------
__global__ void k_rawboxes(const float* __restrict__ in, const int* __restrict__ sq_p,
                           float* __restrict__ out){
    int cell = blockIdx.x*blockDim.x + threadIdx.x;
    if (cell >= NCELLS) return;
    int i = cell >> 9, j = cell & (G-1);
    const float4* p = reinterpret_cast<const float4*>(in + (size_t)cell*100);
    float4 v0 = p[0]; float4 v1 = p[1]; float4 v2 = p[2];
    int sq = *sq_p;
    float jf = (float)j, iff = (float)i;
    float rcx[2] = {v0.z, v1.z}, rcy[2] = {v0.w, v1.w};
    float rw[2]  = {v1.x, v2.x}, rh[2]  = {v1.y, v2.y};
    #pragma unroll
    for (int a = 0; a < 2; a++){
        float cx = __fmul_rn(__fadd_rn(rcx[a], jf), 16.0f);
        float cy = __fmul_rn(__fadd_rn(rcy[a], iff), 16.0f);
        float w = rw[a], h = rh[a];
        if (sq){ w = __fmul_rn(w, w); h = __fmul_rn(h, h); }
        w = __fmul_rn(w, 8192.0f);
        h = __fmul_rn(h, 8192.0f);
        int idx = cell*2 + a;
        ((float4*)out)[idx] = make_float4(cx, cy, w, h);
    }
}

// ---------------- launch ----------------
extern "C" void kernel_launch(void* const* d_in, const int* in_sizes, int n_in,
                              void* d_out, int out_size){
    const float* in = (const float*)d_in[0];
    const int*   sq = (const int*)d_in[1];

    if (out_size >= NBOX*4){   // extract_boxes == 0 path
        k_rawboxes<<<NCELLS/256, 256>>>(in, sq, (float*)d_out);
        return;
    }

    void* histAddr = nullptr; cudaGetSymbolAddress(&histAddr, g_hist);
    void* cntAddr  = nullptr; cudaGetSymbolAddress(&cntAddr,  g_cnt);
    cudaMemsetAsync(histAddr, 0, NBINS*sizeof(int));
    cudaMemsetAsync(cntAddr,  0, NBINS*sizeof(int));

    const int decodeSmem = TILE*CSTRIDE*sizeof(float4);  // 55296
    cudaFuncSetAttribute(k_decode, cudaFuncAttributeMaxDynamicSharedMemorySize, decodeSmem);
    cudaFuncSetAttribute(k_scan,   cudaFuncAttributeMaxDynamicSharedMemorySize, NBINS*4);

    k_decode<<<NCELLS/TILE, TILE, decodeSmem>>>(in, sq);
    k_scan<<<1, 1024, NBINS*4>>>();
    k_scatter<<<NBOX/256, 256>>>();
    k_nms<<<1, 32>>>((float*)d_out, out_size);
}

// round 4
// speedup vs baseline: 1.4953x; 1.3633x over previous
#include <cuda_runtime.h>
#include <cstdint>

#define G 512
#define NCELLS (G*G)          // 262144 cells
#define NBOX (NCELLS*2)       // 524288 boxes
#define NBINS 16384
#define WIN 256
#define SORTC 512             // sort/matrix capacity (power of 2)
#define CAP 512               // fallback window capacity
#define SLOTS (CAP/32)
#define MAXW 2052
#define MAX_OUT 100

// ---------------- device scratch (static globals; no allocation) ----------------
__device__ float4 g_box[NBOX];
__device__ float  g_area[NBOX];
__device__ float  g_score[NBOX];
__device__ int    g_cls[NCELLS];
__device__ unsigned long long g_sorted[NBOX];  // binned (score,~idx) keys
__device__ int    g_hist[NBINS];
__device__ int    g_cnt[NBINS];
__device__ int    g_binStart[NBINS];
__device__ int    g_B[MAXW];
__device__ int    g_total;
__device__ int    g_S;                         // primary prefix size (= g_B[1], <= SORTC)
// sorted primary prefix
__device__ int    g_sidx[SORTC];
__device__ float4 g_sbox[SORTC];
__device__ float  g_sarea[SORTC];
__device__ unsigned g_sdeg[SORTC/32];
__device__ unsigned g_mat[SORTC*16];           // suppression bit matrix, row stride 16 words

__device__ __forceinline__ unsigned binOf(float s){
    return (__float_as_uint(s) - 0x3F000000u) >> 9;
}

// IOU > 0.5 test, float ops ordered exactly like the XLA reference.
__device__ __forceinline__ bool iou_gt(float4 a, float aa, float4 b, float ab){
    float ix1 = fmaxf(a.x, b.x);
    float iy1 = fmaxf(a.y, b.y);
    float ix2 = fminf(a.z, b.z);
    float iy2 = fminf(a.w, b.w);
    float iw  = fmaxf(__fsub_rn(ix2, ix1), 0.0f);
    float ih  = fmaxf(__fsub_rn(iy2, iy1), 0.0f);
    float inter = __fmul_rn(iw, ih);
    float den   = __fadd_rn(__fsub_rn(__fadd_rn(aa, ab), inter), 1e-9f);
    return __fdiv_rn(inter, den) > 0.5f;
}

// reference self-IOU removal test: selected box stays active forever if NOT (a/((a+a-a)+1e-9) > 0.5)
__device__ __forceinline__ bool is_deg(float a){
    float sden = __fadd_rn(__fsub_rn(__fadd_rn(a, a), a), 1e-9f);
    return !(__fdiv_rn(a, sden) > 0.5f);
}

__device__ __forceinline__ unsigned long long shflx_u64(unsigned long long v, int m){
    return __shfl_xor_sync(0xFFFFFFFFu, v, m);
}

// ---------------- K1: decode + score histogram (direct float4) ----------------
__global__ void k_decode(const float* __restrict__ in, const int* __restrict__ sq_p){
    int cell = blockIdx.x*blockDim.x + threadIdx.x;
    if (cell >= NCELLS) return;
    int i = cell >> 9;
    int j = cell & (G-1);
    const float4* p = reinterpret_cast<const float4*>(in + (size_t)cell*100);
    float4 v0 = p[0];   // obj0 obj1 cx0 cy0
    float4 v1 = p[1];   // w0 h0 cx1 cy1
    float4 v2 = p[2];   // w1 h1 cls0 cls1
    float m = v2.z; int am = 0;
    if (v2.w > m){ m = v2.w; am = 1; }
    #pragma unroll
    for (int k = 3; k < 25; k++){
        float4 v = p[k];
        int base = (k-3)*4 + 2;
        if (v.x > m){ m = v.x; am = base;   }
        if (v.y > m){ m = v.y; am = base+1; }
        if (v.z > m){ m = v.z; am = base+2; }
        if (v.w > m){ m = v.w; am = base+3; }
    }
    g_cls[cell] = am;
    int sq = *sq_p;
    float jf = (float)j, iff = (float)i;
    float obj[2]; obj[0] = v0.x; obj[1] = v0.y;
    float rcx[2]; rcx[0] = v0.z; rcx[1] = v1.z;
    float rcy[2]; rcy[0] = v0.w; rcy[1] = v1.w;
    float rw[2];  rw[0]  = v1.x; rw[1]  = v2.x;
    float rh[2];  rh[0]  = v1.y; rh[1]  = v2.y;
    #pragma unroll
    for (int a = 0; a < 2; a++){
        float cx = __fmul_rn(__fadd_rn(rcx[a], jf), 16.0f);
        float cy = __fmul_rn(__fadd_rn(rcy[a], iff), 16.0f);
        float w = rw[a], h = rh[a];
        if (sq){ w = __fmul_rn(w, w); h = __fmul_rn(h, h); }
        w = __fmul_rn(w, 8192.0f);
        h = __fmul_rn(h, 8192.0f);
        float hw = __fmul_rn(w, 0.5f), hh = __fmul_rn(h, 0.5f);
        float x1 = __fsub_rn(cx, hw);
        float y1 = __fsub_rn(cy, hh);
        float x2 = __fsub_rn(__fadd_rn(cx, hw), 1.0f);
        float y2 = __fsub_rn(__fadd_rn(cy, hh), 1.0f);
        float area = __fmul_rn(fmaxf(__fsub_rn(x2, x1), 0.0f),
                               fmaxf(__fsub_rn(y2, y1), 0.0f));
        float sc = __fmul_rn(m, obj[a]);
        int idx = cell*2 + a;
        g_box[idx]   = make_float4(x1, y1, x2, y2);
        g_area[idx]  = area;
        g_score[idx] = sc;
        if (sc > 0.6f) atomicAdd(&g_hist[binOf(sc)], 1);
    }
}

// ---------------- K2: suffix-sum over bins + window boundaries ----------------
__global__ void k_scan(){
    extern __shared__ int smi[];
    __shared__ int part[1024];
    int tid = threadIdx.x;
    const int PER = NBINS/1024;
    int base = tid*PER;
    int vals[PER];
    int run = 0;
    #pragma unroll
    for (int t = 0; t < PER; t++){
        int v = g_hist[(NBINS-1) - (base + t)];
        vals[t] = run;
        run += v;
    }
    part[tid] = run;
    __syncthreads();
    for (int d = 1; d < 1024; d <<= 1){
        int v = (tid >= d) ? part[tid - d] : 0;
        __syncthreads();
        part[tid] += v;
        __syncthreads();
    }
    int off = part[tid] - run;
    int T   = part[1023];
    #pragma unroll
    for (int t = 0; t < PER; t++){
        int j = base + t;
        int s = off + vals[t];
        smi[j] = s;
        g_binStart[(NBINS-1) - j] = s;
    }
    if (tid == 0){ g_total = T; g_B[0] = 0; }
    for (int k = tid; k < MAXW; k += 1024) if (k > 0) g_B[k] = T;
    __syncthreads();
    #pragma unroll
    for (int t = 0; t < PER; t++){
        int j = base + t;
        if (j == 0) continue;
        int s  = smi[j];
        int sp = smi[j-1];
        for (int k = sp/WIN + 1; k*WIN <= s && k < MAXW; k++) g_B[k] = s;
    }
    __syncthreads();
    if (tid == 0){
        int b1 = g_B[1];
        g_S = (b1 <= SORTC) ? b1 : 0;   // pathological clamp -> primary disabled (fallback covers)
    }
}

// ---------------- K3: compact candidates into binned key array ----------------
__global__ void k_scatter(){
    int idx = blockIdx.x*blockDim.x + threadIdx.x;
    if (idx >= NBOX) return;
    float s = g_score[idx];
    if (s > 0.6f){
        unsigned b = binOf(s);
        int pos = g_binStart[b] + atomicAdd(&g_cnt[b], 1);
        unsigned long long key = ((unsigned long long)__float_as_uint(s) << 32)
                               | (unsigned long long)(0xFFFFFFFFu - (unsigned)idx);
        g_sorted[pos] = key;
    }
}

// ---------------- K4a: sort primary prefix (1 CTA, 256 thr) ----------------
__global__ void k_sort(){
    __shared__ unsigned long long sk[SORTC];
    int tid = threadIdx.x;
    int lane = tid & 31;
    int S = g_S;
    for (int c = tid; c < SORTC; c += 256)
        sk[c] = (c < S) ? g_sorted[c] : 0ULL;
    __syncthreads();
    for (int kk = 2; kk <= SORTC; kk <<= 1){
        for (int jj = kk >> 1; jj > 0; jj >>= 1){
            for (int c = tid; c < SORTC; c += 256){
                int cx = c ^ jj;
                if (cx > c){
                    unsigned long long a = sk[c], b = sk[cx];
                    bool sw = ((c & kk) == 0) ? (a < b) : (a > b);
                    if (sw){ sk[c] = b; sk[cx] = a; }
                }
            }
            __syncthreads();
        }
    }
    // emit sorted idx/box/area + degenerate bitmask
    #pragma unroll
    for (int h = 0; h < 2; h++){
        int c = tid + h*256;
        unsigned long long k = sk[c];
        bool valid = (k != 0ULL);
        int idx = valid ? (int)(0xFFFFFFFFu - (unsigned)(k & 0xFFFFFFFFull)) : -1;
        float a = 0.0f;
        if (valid){
            g_sbox[c]  = g_box[idx];
            a = g_area[idx];
        } else {
            g_sbox[c] = make_float4(0.f,0.f,0.f,0.f);
        }
        g_sarea[c] = a;
        g_sidx[c]  = idx;
        bool deg = valid && is_deg(a);
        unsigned w = __ballot_sync(0xFFFFFFFFu, deg);
        if (lane == 0) g_sdeg[c >> 5] = w;
    }
}

// ---------------- K4b: suppression matrix (warp-per-row, chip-wide) ----------------
__global__ void k_matrix(){
    int warp = (blockIdx.x*blockDim.x + threadIdx.x) >> 5;
    int lane = threadIdx.x & 31;
    int S = g_S;
    if (warp >= S) return;
    int NW = (S + 31) >> 5;
    float4 br = g_sbox[warp];
    float  ar = g_sarea[warp];
    for (int b = 0; b < NW; b++){
        int j = b*32 + lane;
        bool bit = false;
        if (j < S) bit = iou_gt(g_sbox[j], g_sarea[j], br, ar);
        unsigned w = __ballot_sync(0xFFFFFFFFu, bit);
        if (lane == 0) g_mat[warp*16 + b] = w;
    }
}

// ---------------- K4c: serial greedy scan (bit-ops) + fallback + output ----------
__global__ void k_final(float* __restrict__ out, int out_size){
    __shared__ unsigned smat[SORTC*16];      // 32 KB
    __shared__ int      s_sidx[SORTC];
    __shared__ unsigned s_deg[SORTC/32];
    __shared__ float4   s_kbox[MAX_OUT];
    __shared__ float    s_karea[MAX_OUT];
    __shared__ int      s_kidx[MAX_OUT];
    __shared__ float4   s_cbox[CAP];
    __shared__ float    s_carea[CAP];
    __shared__ int      s_nk, s_frozen;

    int tid = threadIdx.x;
    int lane = tid & 31;
    int S = g_S;
    int T = g_total;
    int NW = (S + 31) >> 5;

    for (int q = tid; q < S*16; q += 128) smat[q] = g_mat[q];
    for (int q = tid; q < SORTC; q += 128) s_sidx[q] = g_sidx[q];
    if (tid < SORTC/32) s_deg[tid] = g_sdeg[tid];
    if (tid == 0){ s_nk = 0; s_frozen = 0; }
    __syncthreads();

    // ---- primary scan: warp 0, pure bit ops over sorted prefix ----
    if (tid < 32){
        unsigned aw = 0;
        if (lane < NW){
            int rem = S - lane*32;
            aw = (rem >= 32) ? 0xFFFFFFFFu : ((rem > 0) ? ((1u << rem) - 1u) : 0u);
        }
        int nk = 0, frozen = 0;
        while (nk < MAX_OUT){
            unsigned bal = __ballot_sync(0xFFFFFFFFu, aw != 0u);
            if (!bal) break;
            int sl  = __ffs(bal) - 1;
            unsigned w = __shfl_sync(0xFFFFFFFFu, aw, sl);
            int bit = __ffs(w) - 1;
            int c = sl*32 + bit;
            if (lane == 0) s_kidx[nk] = s_sidx[c];
            nk++;
            if ((s_deg[c >> 5] >> (c & 31)) & 1u){ frozen = 1; break; }
            if (lane < NW) aw &= ~smat[c*16 + lane];
            if (lane == sl) aw &= ~(1u << bit);   // paranoia; row self-bit already covers it
        }
        if (lane == 0){ s_nk = nk; s_frozen = frozen; }
    }
    __syncthreads();

    // ---- fallback (rare): continue exact greedy over later windows, warp 0 ----
    if (!s_frozen && s_nk < MAX_OUT && g_B[1] < T){
        // gather kept boxes for prefilter
        for (int k = tid; k < s_nk; k += 128){
            int idx = s_kidx[k];
            s_kbox[k]  = g_box[idx];
            s_karea[k] = g_area[idx];
        }
        __syncthreads();
        if (tid < 32){
            int nk = s_nk, frozen = 0;
            for (int w = 1; w < MAXW-1 && !frozen && nk < MAX_OUT; w++){
                int lo = g_B[w], hi = g_B[w+1];
                if (lo >= T) break;
                if (hi <= lo) continue;
                int size = hi - lo; if (size > CAP) size = CAP;
                unsigned long long key[SLOTS];
                unsigned am = 0;
                #pragma unroll
                for (int t = 0; t < SLOTS; t++){
                    int c = t*32 + lane;
                    unsigned long long k = (c < size) ? g_sorted[lo + c] : 0ULL;
                    key[t] = k;
                    if (k){
                        unsigned idx = 0xFFFFFFFFu - (unsigned)(k & 0xFFFFFFFFull);
                        s_cbox[c]  = g_box[idx];
                        s_carea[c] = g_area[idx];
                        am |= (1u << t);
                    }
                }
                __syncwarp();
                #pragma unroll
                for (int t = 0; t < SLOTS; t++){
                    if (am & (1u << t)){
                        int c = t*32 + lane;
                        float4 b = s_cbox[c]; float ab = s_carea[c];
                        for (int k2 = 0; k2 < nk; k2++)
                            if (iou_gt(b, ab, s_kbox[k2], s_karea[k2])){ am &= ~(1u << t); break; }
                    }
                }
                while (true){
                    unsigned long long best = 0;
                    #pragma unroll
                    for (int t = 0; t < SLOTS; t++)
                        if (((am >> t) & 1) && key[t] > best) best = key[t];
                    #pragma unroll
                    for (int off = 16; off; off >>= 1){
                        unsigned long long o = shflx_u64(best, off);
                        if (o > best) best = o;
                    }
                    if (best == 0) break;
                    int myc = -1;
                    #pragma unroll
                    for (int t = 0; t < SLOTS; t++)
                        if (((am >> t) & 1) && key[t] == best) myc = t*32 + lane;
                    unsigned bal = __ballot_sync(0xFFFFFFFFu, myc >= 0);
                    int src  = __ffs(bal) - 1;
                    int selc = __shfl_sync(0xFFFFFFFFu, myc, src);
                    if (lane == src) am &= ~(1u << (selc >> 5));
                    float4 sb = s_cbox[selc]; float sa = s_carea[selc];
                    if (lane == 0) s_kidx[nk] = (int)(0xFFFFFFFFu - (unsigned)(best & 0xFFFFFFFFull));
                    s_kbox[nk]  = sb;      // warp-uniform values; every lane writes same data
                    s_karea[nk] = sa;
                    nk++;
                    if (is_deg(sa)){ frozen = 1; break; }
                    if (nk == MAX_OUT) break;
                    #pragma unroll
                    for (int t = 0; t < SLOTS; t++){
                        if ((am >> t) & 1){
                            int c = t*32 + lane;
                            if (iou_gt(s_cbox[c], s_carea[c], sb, sa)) am &= ~(1u << t);
                        }
                    }
                }
                __syncwarp();
            }
            if (lane == 0){ s_nk = nk; s_frozen = frozen; }
        }
    }
    __syncthreads();

    // ---- output: [boxes(100,4) | cls_ids(100) | scores(100) | valid(100)] f32 ----
    int nk = s_nk, frozen = s_frozen;
    for (int k = tid; k < MAX_OUT; k += 128){
        int src = (k < nk) ? k : (frozen ? nk - 1 : -1);
        if (src >= 0){
            int idx = s_kidx[src];
            float4 b = g_box[idx];
            if (k*4+3 < out_size){
                out[k*4+0] = b.x; out[k*4+1] = b.y; out[k*4+2] = b.z; out[k*4+3] = b.w;
            }
            if (400+k < out_size) out[400+k] = (float)g_cls[idx >> 1];
            if (500+k < out_size) out[500+k] = g_score[idx];
            if (600+k < out_size) out[600+k] = 1.0f;
        } else {
            if (k*4+3 < out_size){
                out[k*4+0] = 0.0f; out[k*4+1] = 0.0f; out[k*4+2] = 0.0f; out[k*4+3] = 0.0f;
            }
            if (400+k < out_size) out[400+k] = -1.0f;
            if (500+k < out_size) out[500+k] = 0.0f;
            if (600+k < out_size) out[600+k] = 0.0f;
        }
    }
}

// ---------------- fallback: extract_boxes == 0 -> raw den_boxes ----------------
__global__ void k_rawboxes(const float* __restrict__ in, const int* __restrict__ sq_p,
                           float* __restrict__ out){
    int cell = blockIdx.x*blockDim.x + threadIdx.x;
    if (cell >= NCELLS) return;
    int i = cell >> 9, j = cell & (G-1);
    const float4* p = reinterpret_cast<const float4*>(in + (size_t)cell*100);
    float4 v0 = p[0]; float4 v1 = p[1]; float4 v2 = p[2];
    int sq = *sq_p;
    float jf = (float)j, iff = (float)i;
    float rcx[2] = {v0.z, v1.z}, rcy[2] = {v0.w, v1.w};
    float rw[2]  = {v1.x, v2.x}, rh[2]  = {v1.y, v2.y};
    #pragma unroll
    for (int a = 0; a < 2; a++){
        float cx = __fmul_rn(__fadd_rn(rcx[a], jf), 16.0f);
        float cy = __fmul_rn(__fadd_rn(rcy[a], iff), 16.0f);
        float w = rw[a], h = rh[a];
        if (sq){ w = __fmul_rn(w, w); h = __fmul_rn(h, h); }
        w = __fmul_rn(w, 8192.0f);
        h = __fmul_rn(h, 8192.0f);
        int idx = cell*2 + a;
        ((float4*)out)[idx] = make_float4(cx, cy, w, h);
    }
}

// ---------------- launch ----------------
extern "C" void kernel_launch(void* const* d_in, const int* in_sizes, int n_in,
                              void* d_out, int out_size){
    const float* in = (const float*)d_in[0];
    const int*   sq = (const int*)d_in[1];

    if (out_size >= NBOX*4){   // extract_boxes == 0 path
        k_rawboxes<<<NCELLS/256, 256>>>(in, sq, (float*)d_out);
        return;
    }

    void* histAddr = nullptr; cudaGetSymbolAddress(&histAddr, g_hist);
    void* cntAddr  = nullptr; cudaGetSymbolAddress(&cntAddr,  g_cnt);
    cudaMemsetAsync(histAddr, 0, NBINS*sizeof(int));
    cudaMemsetAsync(cntAddr,  0, NBINS*sizeof(int));

    cudaFuncSetAttribute(k_scan, cudaFuncAttributeMaxDynamicSharedMemorySize, NBINS*4);

    k_decode<<<NCELLS/256, 256>>>(in, sq);
    k_scan<<<1, 1024, NBINS*4>>>();
    k_scatter<<<NBOX/256, 256>>>();
    k_sort<<<1, 256>>>();
    k_matrix<<<128, 128>>>();
    k_final<<<1, 128>>>((float*)d_out, out_size);
}